// round 6
// baseline (speedup 1.0000x reference)
#include <cuda_runtime.h>
#include <cuda_bf16.h>
#include <math.h>
#include <stdint.h>

#define KP 800               // 784 padded to multiple of 32
#define NB 4096              // batch

// Scratch (static __device__ arrays -- no runtime allocation)
__device__ __nv_bfloat16 g_AH[NB * KP];         // feats hi  [B][KP]
__device__ __nv_bfloat16 g_AL[NB * KP];         // feats lo
__device__ __nv_bfloat16 g_WH[256 * KP];        // W1 hi    [256][KP]
__device__ __nv_bfloat16 g_WL[256 * KP];        // W1 lo
__device__ float g_h[NB * 256];                 // hidden   [B][256]

// ---------------------------------------------------------------------------
// helpers
// ---------------------------------------------------------------------------
__device__ __forceinline__ uint32_t pack_bf2(float a, float b) {
    uint32_t lo = (uint32_t)__bfloat16_as_ushort(__float2bfloat16(a));
    uint32_t hi = (uint32_t)__bfloat16_as_ushort(__float2bfloat16(b));
    return lo | (hi << 16);
}
__device__ __forceinline__ unsigned long long pk64(float lo, float hi) {
    unsigned long long r;
    asm("mov.b64 %0, {%1, %2};" : "=l"(r) : "f"(lo), "f"(hi));
    return r;
}
__device__ __forceinline__ void upk64(float& lo, float& hi, unsigned long long v) {
    asm("mov.b64 {%0, %1}, %2;" : "=f"(lo), "=f"(hi) : "l"(v));
}
__device__ __forceinline__ unsigned long long fma2(unsigned long long a,
                                                   unsigned long long b,
                                                   unsigned long long c) {
    unsigned long long d;
    asm("fma.rn.f32x2 %0, %1, %2, %3;" : "=l"(d) : "l"(a), "l"(b), "l"(c));
    return d;
}

// ---------------------------------------------------------------------------
// Kernel 1 (fused): blocks [0,B): quanvolution (V computed in-block).
//                   blocks [B,B+256): W1 -> bf16 hi/lo conversion.
// ---------------------------------------------------------------------------
__global__ __launch_bounds__(256) void prep_kernel(
    const float* __restrict__ x, const float* __restrict__ var_angles,
    const float* __restrict__ W1, int nimg) {
    int b = blockIdx.x;
    int t = threadIdx.x;

    if (b >= nimg) {
        // ---- W1 conversion block ----
        int n = b - nimg;                    // 0..255
        const float* wrow = W1 + (size_t)n * 784;
        size_t obase = (size_t)n * KP;
        for (int k = t; k < 784; k += 256) {
            float v = wrow[k];
            __nv_bfloat16 h = __float2bfloat16(v);
            g_WH[obase + k] = h;
            g_WL[obase + k] = __float2bfloat16(v - __bfloat162float(h));
        }
        if (t < 16) {
            g_WH[obase + 784 + t] = __ushort_as_bfloat16(0);
            g_WL[obase + 784 + t] = __ushort_as_bfloat16(0);
        }
        return;
    }

    // ---- quanvolution block ----
    __shared__ __align__(16) float simg[784];
    __shared__ float2 sVp[128];              // sVp[j*8+p] = (V[2p][j], V[2p+1][j])

    const float4* img4 = (const float4*)(x + (size_t)b * 784);
    if (t < 196) ((float4*)simg)[t] = img4[t];

    if (t < 16) {
        // build column j=t of V = (ring*RY(d1))*(ring*RY(d0))
        int j = t;
        float v[16];
        #pragma unroll
        for (int i = 0; i < 16; ++i) v[i] = (i == j) ? 1.0f : 0.0f;
        #pragma unroll
        for (int d = 0; d < 2; ++d) {
            #pragma unroll
            for (int w = 0; w < 4; ++w) {
                float half = var_angles[d * 4 + w] * 0.5f;
                float c = cosf(half), s = sinf(half);
                int mask = 1 << (3 - w);
                #pragma unroll
                for (int i = 0; i < 16; ++i) {
                    if (!(i & mask)) {
                        float v0 = v[i], v1 = v[i | mask];
                        v[i]        = c * v0 - s * v1;
                        v[i | mask] = s * v0 + c * v1;
                    }
                }
            }
            #pragma unroll
            for (int cw = 0; cw < 4; ++cw) {
                int tw = (cw + 1) & 3;
                int cm = 1 << (3 - cw), tm = 1 << (3 - tw);
                #pragma unroll
                for (int i = 0; i < 16; ++i) {
                    if ((i & cm) && !(i & tm)) {
                        float tmp = v[i]; v[i] = v[i | tm]; v[i | tm] = tmp;
                    }
                }
            }
        }
        #pragma unroll
        for (int p = 0; p < 8; ++p) sVp[j * 8 + p] = make_float2(v[2 * p], v[2 * p + 1]);
    }
    __syncthreads();

    if (t < 196) {
        int r = t / 14, c = t % 14;
        float p0 = simg[(2 * r) * 28 + 2 * c];
        float p1 = simg[(2 * r) * 28 + 2 * c + 1];
        float p2 = simg[(2 * r + 1) * 28 + 2 * c];
        float p3 = simg[(2 * r + 1) * 28 + 2 * c + 1];

        float s0, c0, s1, c1, s2, c2, s3, c3;
        __sincosf(0.5f * p0, &s0, &c0);
        __sincosf(0.5f * p1, &s1, &c1);
        __sincosf(0.5f * p2, &s2, &c2);
        __sincosf(0.5f * p3, &s3, &c3);

        float sv[16];
        {
            float ab0 = c0 * c1, ab1 = c0 * s1, ab2 = s0 * c1, ab3 = s0 * s1;
            float cd0 = c2 * c3, cd1 = c2 * s3, cd2 = s2 * c3, cd3 = s2 * s3;
            sv[0] = ab0 * cd0;  sv[1] = ab0 * cd1;  sv[2] = ab0 * cd2;  sv[3] = ab0 * cd3;
            sv[4] = ab1 * cd0;  sv[5] = ab1 * cd1;  sv[6] = ab1 * cd2;  sv[7] = ab1 * cd3;
            sv[8] = ab2 * cd0;  sv[9] = ab2 * cd1;  sv[10] = ab2 * cd2; sv[11] = ab2 * cd3;
            sv[12] = ab3 * cd0; sv[13] = ab3 * cd1; sv[14] = ab3 * cd2; sv[15] = ab3 * cd3;
        }

        // t = V s via packed f32x2 FMA (8 accumulators of 2 rows each)
        unsigned long long acc[8];
        #pragma unroll
        for (int p = 0; p < 8; ++p) acc[p] = 0ull;
        #pragma unroll
        for (int j = 0; j < 16; ++j) {
            unsigned long long bs = pk64(sv[j], sv[j]);
            #pragma unroll
            for (int p = 0; p < 8; ++p) {
                float2 vp = sVp[j * 8 + p];
                acc[p] = fma2(pk64(vp.x, vp.y), bs, acc[p]);
            }
        }

        // feats: f_w = sum_i sign_w(i) t_i^2 ; i = 2p+e
        float f0 = 0.f, f1 = 0.f, f2 = 0.f, f3 = 0.f;
        #pragma unroll
        for (int p = 0; p < 8; ++p) {
            float t0, t1; upk64(t0, t1, acc[p]);
            float q0 = t0 * t0, q1 = t1 * t1;
            float qs = q0 + q1, qd = q0 - q1;
            f3 += qd;
            f0 += (p & 4) ? -qs : qs;
            f1 += (p & 2) ? -qs : qs;
            f2 += (p & 1) ? -qs : qs;
        }

        float h0 = __bfloat162float(__float2bfloat16(f0));
        float h1 = __bfloat162float(__float2bfloat16(f1));
        float h2 = __bfloat162float(__float2bfloat16(f2));
        float h3 = __bfloat162float(__float2bfloat16(f3));
        uint2 H = make_uint2(pack_bf2(f0, f1), pack_bf2(f2, f3));
        uint2 L = make_uint2(pack_bf2(f0 - h0, f1 - h1), pack_bf2(f2 - h2, f3 - h3));
        size_t base = (size_t)b * KP + 4 * t;
        *(uint2*)&g_AH[base] = H;
        *(uint2*)&g_AL[base] = L;
    } else if (t < 200) {
        uint2 z = make_uint2(0u, 0u);
        size_t base = (size_t)b * KP + 784 + 4 * (t - 196);
        *(uint2*)&g_AH[base] = z;
        *(uint2*)&g_AL[base] = z;
    }
}

// ---------------------------------------------------------------------------
// Kernel 2: H = relu(A @ W1^T + b1), bf16x3 tensor-core GEMM.
// BM=64, BN=64, BK=32, 256 threads (8 warps, 4x2), warp tile 16x32,
// 3-stage cp.async pipeline. grid = (4, 64) = 256 CTAs.
// Swizzle: 64B rows (4 x 16B chunks); chunk' = c ^ ((r>>1)&3).
// ---------------------------------------------------------------------------
#define STG 16384
#define OFF_AH 0
#define OFF_AL 4096
#define OFF_WH 8192
#define OFF_WL 12288
#define NKT 25               // KP / 32

__device__ __forceinline__ void ldsm4(uint32_t* r, uint32_t a) {
    asm volatile("ldmatrix.sync.aligned.m8n8.x4.shared.b16 {%0,%1,%2,%3}, [%4];\n"
                 : "=r"(r[0]), "=r"(r[1]), "=r"(r[2]), "=r"(r[3]) : "r"(a));
}
__device__ __forceinline__ void mma16816(float* d, const uint32_t* a, uint32_t b0, uint32_t b1) {
    asm volatile(
        "mma.sync.aligned.m16n8k16.row.col.f32.bf16.bf16.f32 "
        "{%0,%1,%2,%3}, {%4,%5,%6,%7}, {%8,%9}, {%0,%1,%2,%3};\n"
        : "+f"(d[0]), "+f"(d[1]), "+f"(d[2]), "+f"(d[3])
        : "r"(a[0]), "r"(a[1]), "r"(a[2]), "r"(a[3]), "r"(b0), "r"(b1));
}
__device__ __forceinline__ void cp16(uint32_t dst, const void* src) {
    asm volatile("cp.async.cg.shared.global [%0], [%1], 16;\n" :: "r"(dst), "l"(src));
}

__global__ __launch_bounds__(256) void gemm1_kernel(const float* __restrict__ b1) {
    __shared__ __align__(16) unsigned char smem[3 * STG];
    uint32_t sbase = (uint32_t)__cvta_generic_to_shared(smem);
    int t = threadIdx.x;
    int bm = blockIdx.y, bn = blockIdx.x;
    int warp = t >> 5, lane = t & 31;
    int wm = warp >> 1, wn = warp & 1;

    // global-load indexing: 16B chunks, row = t>>2 (0..63), chunk = t&3
    int row = t >> 2, ch = t & 3;
    uint32_t sw = (uint32_t)(row * 64 + ((ch ^ ((row >> 1) & 3)) << 4));
    const size_t a_goff = (size_t)(bm * 64 + row) * KP + ch * 8;
    const size_t w_goff = (size_t)(bn * 64 + row) * KP + ch * 8;

    float acc[4][4];
    #pragma unroll
    for (int nj = 0; nj < 4; ++nj)
        #pragma unroll
        for (int e = 0; e < 4; ++e) acc[nj][e] = 0.f;

    // prologue: stages 0, 1
    #pragma unroll
    for (int s = 0; s < 2; ++s) {
        uint32_t B = sbase + s * STG;
        int k0 = s * 32;
        cp16(B + OFF_AH + sw, g_AH + a_goff + k0);
        cp16(B + OFF_AL + sw, g_AL + a_goff + k0);
        cp16(B + OFF_WH + sw, g_WH + w_goff + k0);
        cp16(B + OFF_WL + sw, g_WL + w_goff + k0);
        asm volatile("cp.async.commit_group;\n");
    }

    int grp = lane >> 3, li = lane & 7;
    for (int kt = 0; kt < NKT; ++kt) {
        if (kt < NKT - 1) asm volatile("cp.async.wait_group 1;\n");
        else              asm volatile("cp.async.wait_group 0;\n");
        __syncthreads();

        if (kt + 2 < NKT) {
            uint32_t B = sbase + ((kt + 2) % 3) * STG;
            int k0 = (kt + 2) * 32;
            cp16(B + OFF_AH + sw, g_AH + a_goff + k0);
            cp16(B + OFF_AL + sw, g_AL + a_goff + k0);
            cp16(B + OFF_WH + sw, g_WH + w_goff + k0);
            cp16(B + OFF_WL + sw, g_WL + w_goff + k0);
            asm volatile("cp.async.commit_group;\n");
        }

        uint32_t B = sbase + (kt % 3) * STG;
        #pragma unroll
        for (int ks = 0; ks < 2; ++ks) {
            int ko = ks * 16;
            uint32_t ah[4], al[4], bh[2][4], bl[2][4];
            // A fragment (m16 x k16)
            {
                int r = wm * 16 + li + ((grp & 1) << 3);
                int ke = ko + ((grp >> 1) << 3);
                uint32_t off = (uint32_t)(r * 64 + (((ke >> 3) ^ ((r >> 1) & 3)) << 4));
                ldsm4(ah, B + OFF_AH + off);
                ldsm4(al, B + OFF_AL + off);
            }
            // B fragments (n32 x k16 as two n16 x k16)
            int rb_l = li + ((grp >> 1) << 3);
            int keb = ko + ((grp & 1) << 3);
            #pragma unroll
            for (int nt = 0; nt < 2; ++nt) {
                int r = wn * 32 + nt * 16 + rb_l;
                uint32_t off = (uint32_t)(r * 64 + (((keb >> 3) ^ ((r >> 1) & 3)) << 4));
                ldsm4(bh[nt], B + OFF_WH + off);
                ldsm4(bl[nt], B + OFF_WL + off);
            }
            #pragma unroll
            for (int nj = 0; nj < 4; ++nj) {
                int nt = nj >> 1, hf = nj & 1;
                mma16816(acc[nj], ah, bh[nt][hf * 2], bh[nt][hf * 2 + 1]);
                mma16816(acc[nj], ah, bl[nt][hf * 2], bl[nt][hf * 2 + 1]);
                mma16816(acc[nj], al, bh[nt][hf * 2], bh[nt][hf * 2 + 1]);
            }
        }
        __syncthreads();
    }

    // epilogue: bias + relu -> g_h
    int mrow = bm * 64 + wm * 16 + (lane >> 2);
    int ncol0 = bn * 64 + wn * 32 + (lane & 3) * 2;
    #pragma unroll
    for (int nj = 0; nj < 4; ++nj) {
        int col = ncol0 + nj * 8;
        float bb0 = __ldg(b1 + col), bb1 = __ldg(b1 + col + 1);
        float2 v0 = make_float2(fmaxf(acc[nj][0] + bb0, 0.f),
                                fmaxf(acc[nj][1] + bb1, 0.f));
        float2 v1 = make_float2(fmaxf(acc[nj][2] + bb0, 0.f),
                                fmaxf(acc[nj][3] + bb1, 0.f));
        *(float2*)&g_h[(size_t)mrow * 256 + col] = v0;
        *(float2*)&g_h[(size_t)(mrow + 8) * 256 + col] = v1;
    }
}

// ---------------------------------------------------------------------------
// Kernel 3: logits + log_softmax. 32 rows/block, one warp per row.
// ---------------------------------------------------------------------------
__global__ __launch_bounds__(1024) void head_kernel(
    const float* __restrict__ W2, const float* __restrict__ b2,
    float* __restrict__ out) {
    __shared__ float sW[2560];
    __shared__ float sb[10];
    int t = threadIdx.x;
    for (int i = t; i < 2560; i += 1024) sW[i] = W2[i];
    if (t < 10) sb[t] = b2[t];
    __syncthreads();

    int warp = t >> 5, lane = t & 31;
    int m = blockIdx.x * 32 + warp;
    const float* hr = g_h + (size_t)m * 256;

    float h8[8];
    #pragma unroll
    for (int i = 0; i < 8; ++i) h8[i] = hr[lane + 32 * i];

    float p[10];
    #pragma unroll
    for (int j = 0; j < 10; ++j) {
        float s = 0.f;
        #pragma unroll
        for (int i = 0; i < 8; ++i) s += h8[i] * sW[j * 256 + lane + 32 * i];
        p[j] = s;
    }
    #pragma unroll
    for (int o = 16; o > 0; o >>= 1)
        #pragma unroll
        for (int j = 0; j < 10; ++j) p[j] += __shfl_xor_sync(0xffffffffu, p[j], o);
    #pragma unroll
    for (int j = 0; j < 10; ++j) p[j] += sb[j];

    float mx = p[0];
    #pragma unroll
    for (int j = 1; j < 10; ++j) mx = fmaxf(mx, p[j]);
    float sum = 0.f;
    #pragma unroll
    for (int j = 0; j < 10; ++j) sum += expf(p[j] - mx);
    float lse = mx + logf(sum);

    if (lane < 10) {
        float v;
        switch (lane) {
            case 0: v = p[0]; break; case 1: v = p[1]; break;
            case 2: v = p[2]; break; case 3: v = p[3]; break;
            case 4: v = p[4]; break; case 5: v = p[5]; break;
            case 6: v = p[6]; break; case 7: v = p[7]; break;
            case 8: v = p[8]; break; default: v = p[9]; break;
        }
        out[m * 10 + lane] = v - lse;
    }
}

// ---------------------------------------------------------------------------
extern "C" void kernel_launch(void* const* d_in, const int* in_sizes, int n_in,
                              void* d_out, int out_size) {
    const float* x   = (const float*)d_in[0];   // [B,1,28,28]
    const float* var = (const float*)d_in[1];   // [2,4]
    const float* W1  = (const float*)d_in[2];   // [256,784]
    const float* b1  = (const float*)d_in[3];   // [256]
    const float* W2  = (const float*)d_in[4];   // [10,256]
    const float* b2  = (const float*)d_in[5];   // [10]
    float* out = (float*)d_out;

    int B = in_sizes[0] / 784;                  // 4096

    prep_kernel<<<B + 256, 256>>>(x, var, W1, B);
    dim3 grid1(4, B / 64);
    gemm1_kernel<<<grid1, 256>>>(b1);
    head_kernel<<<B / 32, 1024>>>(W2, b2, out);
}

// round 9
// speedup vs baseline: 1.3616x; 1.3616x over previous
#include <cuda_runtime.h>
#include <cuda_bf16.h>
#include <math.h>
#include <stdint.h>

#define KP 800               // 784 padded to multiple of 32
#define NB 4096              // batch

// Scratch (static __device__ arrays -- no runtime allocation)
__device__ __nv_bfloat16 g_AH[NB * KP];         // feats hi  [B][KP]
__device__ __nv_bfloat16 g_AL[NB * KP];         // feats lo
__device__ __nv_bfloat16 g_WH[256 * KP];        // W1 hi    [256][KP]
__device__ __nv_bfloat16 g_WL[256 * KP];        // W1 lo
__device__ float g_h[NB * 256];                 // hidden   [B][256]

// ---------------------------------------------------------------------------
// helpers
// ---------------------------------------------------------------------------
__device__ __forceinline__ uint32_t pack_bf2(float a, float b) {
    uint32_t lo = (uint32_t)__bfloat16_as_ushort(__float2bfloat16(a));
    uint32_t hi = (uint32_t)__bfloat16_as_ushort(__float2bfloat16(b));
    return lo | (hi << 16);
}

// ---------------------------------------------------------------------------
// Kernel 1 (fused): blocks [0,B): quanvolution.  blocks [B,B+256): W1 -> bf16.
//
// Circuit algebra: RY(p)RY(a0) = RY(p+a0) keeps the encoder+depth0 layer a
// tensor-product state. CNOT rings are pure basis permutations (compile-time
// relabel F). Depth-1 RY layer = 4 register butterfly passes with 8
// warp-uniform coefficients. Measurement signs read bit w of F(i).
//   F[i]: b0'=b1^b2^b3, b1'=b0^b1, b2'=b0^b1^b2, b3'=b0^b1^b2^b3
// ---------------------------------------------------------------------------
__global__ __launch_bounds__(256) void prep_kernel(
    const float* __restrict__ x, const float* __restrict__ var_angles,
    const float* __restrict__ W1, int nimg) {
    int b = blockIdx.x;
    int t = threadIdx.x;

    if (b >= nimg) {
        // ---- W1 conversion block ----
        int n = b - nimg;                    // 0..255
        const float* wrow = W1 + (size_t)n * 784;
        size_t obase = (size_t)n * KP;
        for (int k = t; k < 784; k += 256) {
            float v = wrow[k];
            __nv_bfloat16 h = __float2bfloat16(v);
            g_WH[obase + k] = h;
            g_WL[obase + k] = __float2bfloat16(v - __bfloat162float(h));
        }
        if (t < 16) {
            g_WH[obase + 784 + t] = __ushort_as_bfloat16(0);
            g_WL[obase + 784 + t] = __ushort_as_bfloat16(0);
        }
        return;
    }

    // ---- quanvolution block: one image, one thread per patch ----
    __shared__ __align__(16) float simg[784];
    __shared__ float sA0h[4];                // 0.5 * var_angles[0][w]
    __shared__ float sCB[4], sSB[4];         // cos/sin(0.5 * var_angles[1][w])

    const float4* img4 = (const float4*)(x + (size_t)b * 784);
    if (t < 196) ((float4*)simg)[t] = img4[t];
    if (t < 4) {
        sA0h[t] = 0.5f * var_angles[t];
        float cb, sb;
        __sincosf(0.5f * var_angles[4 + t], &sb, &cb);
        sCB[t] = cb; sSB[t] = sb;
    }
    __syncthreads();

    if (t < 196) {
        int r = t / 14, c = t % 14;
        float p0 = simg[(2 * r) * 28 + 2 * c];
        float p1 = simg[(2 * r) * 28 + 2 * c + 1];
        float p2 = simg[(2 * r + 1) * 28 + 2 * c];
        float p3 = simg[(2 * r + 1) * 28 + 2 * c + 1];

        // fused encoder + depth-0 RY: angle = 0.5*pixel + 0.5*a0
        float s0, c0, s1, c1, s2, c2, s3, c3;
        __sincosf(0.5f * p0 + sA0h[0], &s0, &c0);
        __sincosf(0.5f * p1 + sA0h[1], &s1, &c1);
        __sincosf(0.5f * p2 + sA0h[2], &s2, &c2);
        __sincosf(0.5f * p3 + sA0h[3], &s3, &c3);

        // product state sv[i], bit3=wire0 .. bit0=wire3
        float sv[16];
        {
            float ab0 = c0 * c1, ab1 = c0 * s1, ab2 = s0 * c1, ab3 = s0 * s1;
            float cd0 = c2 * c3, cd1 = c2 * s3, cd2 = s2 * c3, cd3 = s2 * s3;
            sv[0] = ab0 * cd0;  sv[1] = ab0 * cd1;  sv[2] = ab0 * cd2;  sv[3] = ab0 * cd3;
            sv[4] = ab1 * cd0;  sv[5] = ab1 * cd1;  sv[6] = ab1 * cd2;  sv[7] = ab1 * cd3;
            sv[8] = ab2 * cd0;  sv[9] = ab2 * cd1;  sv[10] = ab2 * cd2; sv[11] = ab2 * cd3;
            sv[12] = ab3 * cd0; sv[13] = ab3 * cd1; sv[14] = ab3 * cd2; sv[15] = ab3 * cd3;
        }

        // CNOT-ring permutation (compile-time relabel)
        const int F[16] = {0, 9, 11, 2, 15, 6, 4, 13, 7, 14, 12, 5, 8, 1, 3, 10};
        float u[16];
        #pragma unroll
        for (int i = 0; i < 16; ++i) u[F[i]] = sv[i];

        // depth-1 RY butterflies (register-resident, uniform coefficients)
        #pragma unroll
        for (int w = 0; w < 4; ++w) {
            int m = 8 >> w;
            float cb = sCB[w], sb = sSB[w];
            #pragma unroll
            for (int i = 0; i < 16; ++i) {
                if (!(i & m)) {
                    float t0 = u[i], t1 = u[i | m];
                    u[i]     = cb * t0 - sb * t1;
                    u[i | m] = sb * t0 + cb * t1;
                }
            }
        }

        // ring2 permutation folded into the measurement signs:
        // f_w = sum_i sign(bit_w(F(i))) * u[i]^2
        float f0 = 0.f, f1 = 0.f, f2 = 0.f, f3 = 0.f;
        #pragma unroll
        for (int i = 0; i < 16; ++i) {
            float q = u[i] * u[i];
            int fi = F[i];
            f0 += (fi & 8) ? -q : q;
            f1 += (fi & 4) ? -q : q;
            f2 += (fi & 2) ? -q : q;
            f3 += (fi & 1) ? -q : q;
        }

        float h0 = __bfloat162float(__float2bfloat16(f0));
        float h1 = __bfloat162float(__float2bfloat16(f1));
        float h2 = __bfloat162float(__float2bfloat16(f2));
        float h3 = __bfloat162float(__float2bfloat16(f3));
        uint2 H = make_uint2(pack_bf2(f0, f1), pack_bf2(f2, f3));
        uint2 L = make_uint2(pack_bf2(f0 - h0, f1 - h1), pack_bf2(f2 - h2, f3 - h3));
        size_t base = (size_t)b * KP + 4 * t;
        *(uint2*)&g_AH[base] = H;
        *(uint2*)&g_AL[base] = L;
    } else if (t < 200) {
        uint2 z = make_uint2(0u, 0u);
        size_t base = (size_t)b * KP + 784 + 4 * (t - 196);
        *(uint2*)&g_AH[base] = z;
        *(uint2*)&g_AL[base] = z;
    }
}

// ---------------------------------------------------------------------------
// Kernel 2: H = relu(A @ W1^T + b1), bf16x3 tensor-core GEMM.
// BM=64, BN=64, BK=32, 256 threads (8 warps, 4x2), warp tile 16x32,
// 3-stage cp.async pipeline. grid = (4, 64) = 256 CTAs.
// ---------------------------------------------------------------------------
#define STG 16384
#define OFF_AH 0
#define OFF_AL 4096
#define OFF_WH 8192
#define OFF_WL 12288
#define NKT 25               // KP / 32

__device__ __forceinline__ void ldsm4(uint32_t* r, uint32_t a) {
    asm volatile("ldmatrix.sync.aligned.m8n8.x4.shared.b16 {%0,%1,%2,%3}, [%4];\n"
                 : "=r"(r[0]), "=r"(r[1]), "=r"(r[2]), "=r"(r[3]) : "r"(a));
}
__device__ __forceinline__ void mma16816(float* d, const uint32_t* a, uint32_t b0, uint32_t b1) {
    asm volatile(
        "mma.sync.aligned.m16n8k16.row.col.f32.bf16.bf16.f32 "
        "{%0,%1,%2,%3}, {%4,%5,%6,%7}, {%8,%9}, {%0,%1,%2,%3};\n"
        : "+f"(d[0]), "+f"(d[1]), "+f"(d[2]), "+f"(d[3])
        : "r"(a[0]), "r"(a[1]), "r"(a[2]), "r"(a[3]), "r"(b0), "r"(b1));
}
__device__ __forceinline__ void cp16(uint32_t dst, const void* src) {
    asm volatile("cp.async.cg.shared.global [%0], [%1], 16;\n" :: "r"(dst), "l"(src));
}

__global__ __launch_bounds__(256) void gemm1_kernel(const float* __restrict__ b1) {
    __shared__ __align__(16) unsigned char smem[3 * STG];
    uint32_t sbase = (uint32_t)__cvta_generic_to_shared(smem);
    int t = threadIdx.x;
    int bm = blockIdx.y, bn = blockIdx.x;
    int warp = t >> 5, lane = t & 31;
    int wm = warp >> 1, wn = warp & 1;

    int row = t >> 2, ch = t & 3;
    uint32_t sw = (uint32_t)(row * 64 + ((ch ^ ((row >> 1) & 3)) << 4));
    const size_t a_goff = (size_t)(bm * 64 + row) * KP + ch * 8;
    const size_t w_goff = (size_t)(bn * 64 + row) * KP + ch * 8;

    float acc[4][4];
    #pragma unroll
    for (int nj = 0; nj < 4; ++nj)
        #pragma unroll
        for (int e = 0; e < 4; ++e) acc[nj][e] = 0.f;

    #pragma unroll
    for (int s = 0; s < 2; ++s) {
        uint32_t B = sbase + s * STG;
        int k0 = s * 32;
        cp16(B + OFF_AH + sw, g_AH + a_goff + k0);
        cp16(B + OFF_AL + sw, g_AL + a_goff + k0);
        cp16(B + OFF_WH + sw, g_WH + w_goff + k0);
        cp16(B + OFF_WL + sw, g_WL + w_goff + k0);
        asm volatile("cp.async.commit_group;\n");
    }

    int grp = lane >> 3, li = lane & 7;
    for (int kt = 0; kt < NKT; ++kt) {
        if (kt < NKT - 1) asm volatile("cp.async.wait_group 1;\n");
        else              asm volatile("cp.async.wait_group 0;\n");
        __syncthreads();

        if (kt + 2 < NKT) {
            uint32_t B = sbase + ((kt + 2) % 3) * STG;
            int k0 = (kt + 2) * 32;
            cp16(B + OFF_AH + sw, g_AH + a_goff + k0);
            cp16(B + OFF_AL + sw, g_AL + a_goff + k0);
            cp16(B + OFF_WH + sw, g_WH + w_goff + k0);
            cp16(B + OFF_WL + sw, g_WL + w_goff + k0);
            asm volatile("cp.async.commit_group;\n");
        }

        uint32_t B = sbase + (kt % 3) * STG;
        #pragma unroll
        for (int ks = 0; ks < 2; ++ks) {
            int ko = ks * 16;
            uint32_t ah[4], al[4], bh[2][4], bl[2][4];
            {
                int r = wm * 16 + li + ((grp & 1) << 3);
                int ke = ko + ((grp >> 1) << 3);
                uint32_t off = (uint32_t)(r * 64 + (((ke >> 3) ^ ((r >> 1) & 3)) << 4));
                ldsm4(ah, B + OFF_AH + off);
                ldsm4(al, B + OFF_AL + off);
            }
            int rb_l = li + ((grp >> 1) << 3);
            int keb = ko + ((grp & 1) << 3);
            #pragma unroll
            for (int nt = 0; nt < 2; ++nt) {
                int r = wn * 32 + nt * 16 + rb_l;
                uint32_t off = (uint32_t)(r * 64 + (((keb >> 3) ^ ((r >> 1) & 3)) << 4));
                ldsm4(bh[nt], B + OFF_WH + off);
                ldsm4(bl[nt], B + OFF_WL + off);
            }
            #pragma unroll
            for (int nj = 0; nj < 4; ++nj) {
                int nt = nj >> 1, hf = nj & 1;
                mma16816(acc[nj], ah, bh[nt][hf * 2], bh[nt][hf * 2 + 1]);
                mma16816(acc[nj], ah, bl[nt][hf * 2], bl[nt][hf * 2 + 1]);
                mma16816(acc[nj], al, bh[nt][hf * 2], bh[nt][hf * 2 + 1]);
            }
        }
        __syncthreads();
    }

    int mrow = bm * 64 + wm * 16 + (lane >> 2);
    int ncol0 = bn * 64 + wn * 32 + (lane & 3) * 2;
    #pragma unroll
    for (int nj = 0; nj < 4; ++nj) {
        int col = ncol0 + nj * 8;
        float bb0 = __ldg(b1 + col), bb1 = __ldg(b1 + col + 1);
        float2 v0 = make_float2(fmaxf(acc[nj][0] + bb0, 0.f),
                                fmaxf(acc[nj][1] + bb1, 0.f));
        float2 v1 = make_float2(fmaxf(acc[nj][2] + bb0, 0.f),
                                fmaxf(acc[nj][3] + bb1, 0.f));
        *(float2*)&g_h[(size_t)mrow * 256 + col] = v0;
        *(float2*)&g_h[(size_t)(mrow + 8) * 256 + col] = v1;
    }
}

// ---------------------------------------------------------------------------
// Kernel 3: logits + log_softmax. 32 rows/block, one warp per row.
// ---------------------------------------------------------------------------
__global__ __launch_bounds__(1024) void head_kernel(
    const float* __restrict__ W2, const float* __restrict__ b2,
    float* __restrict__ out) {
    __shared__ float sW[2560];
    __shared__ float sb[10];
    int t = threadIdx.x;
    for (int i = t; i < 2560; i += 1024) sW[i] = W2[i];
    if (t < 10) sb[t] = b2[t];
    __syncthreads();

    int warp = t >> 5, lane = t & 31;
    int m = blockIdx.x * 32 + warp;
    const float* hr = g_h + (size_t)m * 256;

    float h8[8];
    #pragma unroll
    for (int i = 0; i < 8; ++i) h8[i] = hr[lane + 32 * i];

    float p[10];
    #pragma unroll
    for (int j = 0; j < 10; ++j) {
        float s = 0.f;
        #pragma unroll
        for (int i = 0; i < 8; ++i) s += h8[i] * sW[j * 256 + lane + 32 * i];
        p[j] = s;
    }
    #pragma unroll
    for (int o = 16; o > 0; o >>= 1)
        #pragma unroll
        for (int j = 0; j < 10; ++j) p[j] += __shfl_xor_sync(0xffffffffu, p[j], o);
    #pragma unroll
    for (int j = 0; j < 10; ++j) p[j] += sb[j];

    float mx = p[0];
    #pragma unroll
    for (int j = 1; j < 10; ++j) mx = fmaxf(mx, p[j]);
    float sum = 0.f;
    #pragma unroll
    for (int j = 0; j < 10; ++j) sum += expf(p[j] - mx);
    float lse = mx + logf(sum);

    if (lane < 10) {
        float v;
        switch (lane) {
            case 0: v = p[0]; break; case 1: v = p[1]; break;
            case 2: v = p[2]; break; case 3: v = p[3]; break;
            case 4: v = p[4]; break; case 5: v = p[5]; break;
            case 6: v = p[6]; break; case 7: v = p[7]; break;
            case 8: v = p[8]; break; default: v = p[9]; break;
        }
        out[m * 10 + lane] = v - lse;
    }
}

// ---------------------------------------------------------------------------
extern "C" void kernel_launch(void* const* d_in, const int* in_sizes, int n_in,
                              void* d_out, int out_size) {
    const float* x   = (const float*)d_in[0];   // [B,1,28,28]
    const float* var = (const float*)d_in[1];   // [2,4]
    const float* W1  = (const float*)d_in[2];   // [256,784]
    const float* b1  = (const float*)d_in[3];   // [256]
    const float* W2  = (const float*)d_in[4];   // [10,256]
    const float* b2  = (const float*)d_in[5];   // [10]
    float* out = (float*)d_out;

    int B = in_sizes[0] / 784;                  // 4096

    prep_kernel<<<B + 256, 256>>>(x, var, W1, B);
    dim3 grid1(4, B / 64);
    gemm1_kernel<<<grid1, 256>>>(b1);
    head_kernel<<<B / 32, 1024>>>(W2, b2, out);
}